// round 13
// baseline (speedup 1.0000x reference)
#include <cuda_runtime.h>
#include <math.h>

#define NN 4096
#define MM 4096
typedef unsigned long long u64;

// x row record: 80 floats:
//   [0:8)   A dup   {A0,A0,A1,A1,A2,A2,A3,A3}
//   [8:16)  x dup   {x0,x0,...,x3,x3}
//   [16+16q:32+16q) Xa dup(8), Xb dup(8)
__device__ float4 g_x[NN * 20];
// y pair record (cols 2jp, 2jp+1): 108 floats (104 used):
//   [0:8)   B pairs {B0(j),B0(j+1),B1(j),B1(j+1),...}
//   [8+24q:32+24q)  W pairs(8), Ya pairs(8), Yb pairs(8)
__device__ float4 g_y[(MM / 2) * 27];

#define TWOPI 6.283185307179586f
#define LOG2E 1.4426950408889634f
// G = -2*pi^2*log2(e)
#define GCONST (-28.477805973f)

#define SX_FLOATS (128 * 80)
#define SY_FLOATS (32 * 108)
#define SMEM_BYTES ((SX_FLOATS + SY_FLOATS) * 4)

__device__ __forceinline__ float ex2f(float x) {
    float r; asm("ex2.approx.ftz.f32 %0, %1;" : "=f"(r) : "f"(x)); return r;
}
__device__ __forceinline__ u64 fma2(u64 a, u64 b, u64 c) {
    u64 d; asm("fma.rn.f32x2 %0, %1, %2, %3;" : "=l"(d) : "l"(a), "l"(b), "l"(c)); return d;
}
__device__ __forceinline__ u64 add2(u64 a, u64 b) {
    u64 d; asm("add.rn.f32x2 %0, %1, %2;" : "=l"(d) : "l"(a), "l"(b)); return d;
}
__device__ __forceinline__ u64 mul2(u64 a, u64 b) {
    u64 d; asm("mul.rn.f32x2 %0, %1, %2;" : "=l"(d) : "l"(a), "l"(b)); return d;
}
__device__ __forceinline__ u64 pack2(float lo, float hi) {
    u64 d; asm("mov.b64 %0, {%1, %2};" : "=l"(d) : "f"(lo), "f"(hi)); return d;
}
__device__ __forceinline__ u64 ex2_2(u64 a) {
    float lo, hi;
    asm("mov.b64 {%0, %1}, %2;" : "=f"(lo), "=f"(hi) : "l"(a));
    return pack2(ex2f(lo), ex2f(hi));
}
__device__ __forceinline__ u64 d2u(double d) { return __double_as_longlong(d); }

__global__ void sm_precompute(const float* __restrict__ x,
                              const float* __restrict__ y,
                              const float* __restrict__ lw,
                              const float* __restrict__ rm,
                              const float* __restrict__ lv)
{
    int idx = blockIdx.x * blockDim.x + threadIdx.x;
    if (idx >= NN + MM) return;
    bool isx = idx < NN;
    int row = isx ? idx : idx - NN;

    const float* t = (isx ? x : y) + row * 4;
    float td[4];
#pragma unroll
    for (int d = 0; d < 4; d++) td[d] = t[d];

#pragma unroll
    for (int q = 0; q < 4; q++) {
        float a = 0.0f;
        float c[4], s[4], vq[4];
#pragma unroll
        for (int d = 0; d < 4; d++) {
            vq[d] = expf(lv[q * 4 + d]);
            a = fmaf(vq[d], td[d] * td[d], a);
            float th = TWOPI * rm[q * 4 + d] * td[d];
            sincosf(th, &s[d], &c[d]);
        }
        float P[8];
        P[0] = c[0] * c[1]; P[1] = c[0] * s[1]; P[2] = s[0] * c[1]; P[3] = s[0] * s[1];
        P[4] = c[2] * c[3]; P[5] = c[2] * s[3]; P[6] = s[2] * c[3]; P[7] = s[2] * s[3];

        if (isx) {
            float* o = (float*)g_x + row * 80;
            float Aq = GCONST * a;
            o[2 * q] = Aq; o[2 * q + 1] = Aq;
            if (q == 0) {
#pragma unroll
                for (int d = 0; d < 4; d++) { o[8 + 2 * d] = td[d]; o[9 + 2 * d] = td[d]; }
            }
            float* b = o + 16 + 16 * q;
#pragma unroll
            for (int k = 0; k < 4; k++) { b[2 * k] = P[k];      b[2 * k + 1] = P[k]; }
#pragma unroll
            for (int k = 0; k < 4; k++) { b[8 + 2 * k] = P[4 + k]; b[9 + 2 * k] = P[4 + k]; }
        } else {
            float* o = (float*)g_y + (row >> 1) * 108;
            int sl = row & 1;
            o[2 * q + sl] = GCONST * a + lw[q] * LOG2E;
            float* b = o + 8 + 24 * q;
#pragma unroll
            for (int d = 0; d < 4; d++) b[2 * d + sl] = -2.0f * GCONST * vq[d] * td[d];
#pragma unroll
            for (int k = 0; k < 4; k++) b[8 + 2 * k + sl] = P[k];
#pragma unroll
            for (int k = 0; k < 4; k++) b[16 + 2 * k + sl] = P[4 + k];
        }
    }
}

// Block tile: 128 x-rows x 64 y-cols (32 pair-cols).
// Thread tile: I=8 rows, C=2 pair-cols. 256 threads, 2 blocks/SM.
// q-loop ROLLED (bounds live set, no cross-q hoisting -> no spills).
// Inside each q: per pair-column c, phase A builds all 8 exp args and
// batches the ex2's into e[8]; phase B does the cos dots + accumulate.
// Halved y live-set (9 then 8 u64) leaves ~40 regs of slack so ptxas can
// keep multiple i-iterations' loads in flight.
__global__ void __launch_bounds__(256, 2)
sm_main(float* __restrict__ out)
{
    extern __shared__ float smem[];
    float* sx = smem;                 // 128*80 floats = 40 KB
    float* sy = smem + SX_FLOATS;     // 32*108 floats = 13.5 KB

    const int n0 = blockIdx.y * 128;
    const int m0 = blockIdx.x * 64;

    {
        const float4* gx = g_x + n0 * 20;
        float4* s4 = (float4*)sx;
#pragma unroll 1
        for (int i = threadIdx.x; i < 2560; i += 256) s4[i] = gx[i];
        const float4* gy = g_y + (m0 / 2) * 27;
        float4* t4 = (float4*)sy;
#pragma unroll 1
        for (int i = threadIdx.x; i < 864; i += 256) t4[i] = gy[i];
    }
    __syncthreads();

    const int ti = threadIdx.x >> 4;   // 0..15 : rows ti + 16*i, i<8
    const int tj = threadIdx.x & 15;   // 0..15 : pair-cols tj + 16*c, c<2

    const float* xbase = sx + ti * 80;

    u64 acc[8][2];
#pragma unroll
    for (int i = 0; i < 8; i++) { acc[i][0] = 0ull; acc[i][1] = 0ull; }

#pragma unroll 1
    for (int q = 0; q < 4; q++) {
#pragma unroll
        for (int c = 0; c < 2; c++) {
            const float* yr = sy + (tj + 16 * c) * 108;
            const float* yq = yr + 8 + 24 * q;

            // ---------- phase A: exp args + batched ex2 ----------
            u64 Bp = *(const u64*)(yr + 2 * q);
            double2 w0 = *(const double2*)(yq);
            double2 w1 = *(const double2*)(yq + 4);
            u64 Wp0 = d2u(w0.x), Wp1 = d2u(w0.y), Wp2 = d2u(w1.x), Wp3 = d2u(w1.y);

            u64 e[8];
#pragma unroll
            for (int i = 0; i < 8; i++) {
                const float* xr = xbase + i * 1280;   // (ti + 16*i) * 80
                u64 Ap = *(const u64*)(xr + 2 * q);
                double2 x0 = *(const double2*)(xr + 8);
                double2 x1 = *(const double2*)(xr + 12);
                u64 arg = add2(Ap, Bp);
                arg = fma2(d2u(x0.x), Wp0, arg);
                arg = fma2(d2u(x0.y), Wp1, arg);
                arg = fma2(d2u(x1.x), Wp2, arg);
                arg = fma2(d2u(x1.y), Wp3, arg);
                e[i] = ex2_2(arg);
            }

            // ---------- phase B: cos dots + accumulate ----------
            double2 a0 = *(const double2*)(yq + 8);
            double2 a1 = *(const double2*)(yq + 12);
            u64 Ya0 = d2u(a0.x), Ya1 = d2u(a0.y), Ya2 = d2u(a1.x), Ya3 = d2u(a1.y);
            double2 b0 = *(const double2*)(yq + 16);
            double2 b1 = *(const double2*)(yq + 20);
            u64 Yb0 = d2u(b0.x), Yb1 = d2u(b0.y), Yb2 = d2u(b1.x), Yb3 = d2u(b1.y);

#pragma unroll
            for (int i = 0; i < 8; i++) {
                const float* xq = xbase + i * 1280 + 16 + 16 * q;
                double2 p0 = *(const double2*)(xq);
                double2 p1 = *(const double2*)(xq + 4);
                double2 r0 = *(const double2*)(xq + 8);
                double2 r1 = *(const double2*)(xq + 12);
                u64 ta = mul2(d2u(p0.x), Ya0);
                ta = fma2(d2u(p0.y), Ya1, ta);
                ta = fma2(d2u(p1.x), Ya2, ta);
                ta = fma2(d2u(p1.y), Ya3, ta);
                u64 tb = mul2(d2u(r0.x), Yb0);
                tb = fma2(d2u(r0.y), Yb1, tb);
                tb = fma2(d2u(r1.x), Yb2, tb);
                tb = fma2(d2u(r1.y), Yb3, tb);
                acc[i][c] = fma2(e[i], mul2(ta, tb), acc[i][c]);
            }
        }
    }

#pragma unroll
    for (int i = 0; i < 8; i++) {
        float* row = out + (size_t)(n0 + ti + 16 * i) * MM + m0 + 2 * tj;
        *(u64*)(row)      = acc[i][0];
        *(u64*)(row + 32) = acc[i][1];
    }
}

extern "C" void kernel_launch(void* const* d_in, const int* in_sizes, int n_in,
                              void* d_out, int out_size)
{
    const float* x  = (const float*)d_in[0];
    const float* y  = (const float*)d_in[1];
    const float* lw = (const float*)d_in[2];
    const float* rm = (const float*)d_in[3];
    const float* lv = (const float*)d_in[4];
    float* out = (float*)d_out;

    // Opt in to >48KB dynamic smem. Host-side attribute set: no allocation,
    // not stream-ordered, deterministic — graph-capture safe. Idempotent.
    cudaFuncSetAttribute(sm_main, cudaFuncAttributeMaxDynamicSharedMemorySize,
                         SMEM_BYTES);

    sm_precompute<<<(NN + MM + 255) / 256, 256>>>(x, y, lw, rm, lv);

    dim3 grid(MM / 64, NN / 128);
    sm_main<<<grid, 256, SMEM_BYTES>>>(out);
}

// round 16
// speedup vs baseline: 2.7831x; 2.7831x over previous
#include <cuda_runtime.h>
#include <math.h>

#define NN 4096
#define MM 4096
typedef unsigned long long u64;

// x row record: 80 floats:
//   [0:8)   A dup   {A0,A0,A1,A1,A2,A2,A3,A3}
//   [8:16)  x dup   {x0,x0,...,x3,x3}
//   [16+16q:32+16q) Xa dup(8), Xb dup(8)
__device__ float4 g_x[NN * 20];
// y pair record (cols 2jp, 2jp+1): 108 floats (104 used):
//   [0:8)   B pairs {B0(j),B0(j+1),B1(j),B1(j+1),...}
//   [8+24q:32+24q)  W pairs(8), Ya pairs(8), Yb pairs(8)
__device__ float4 g_y[(MM / 2) * 27];

#define TWOPI 6.283185307179586f
#define LOG2E 1.4426950408889634f
// G = -2*pi^2*log2(e)
#define GCONST (-28.477805973f)

__device__ __forceinline__ float ex2f(float x) {
    float r; asm("ex2.approx.ftz.f32 %0, %1;" : "=f"(r) : "f"(x)); return r;
}
__device__ __forceinline__ u64 fma2(u64 a, u64 b, u64 c) {
    u64 d; asm("fma.rn.f32x2 %0, %1, %2, %3;" : "=l"(d) : "l"(a), "l"(b), "l"(c)); return d;
}
__device__ __forceinline__ u64 add2(u64 a, u64 b) {
    u64 d; asm("add.rn.f32x2 %0, %1, %2;" : "=l"(d) : "l"(a), "l"(b)); return d;
}
__device__ __forceinline__ u64 mul2(u64 a, u64 b) {
    u64 d; asm("mul.rn.f32x2 %0, %1, %2;" : "=l"(d) : "l"(a), "l"(b)); return d;
}
__device__ __forceinline__ u64 pack2(float lo, float hi) {
    u64 d; asm("mov.b64 %0, {%1, %2};" : "=l"(d) : "f"(lo), "f"(hi)); return d;
}
__device__ __forceinline__ u64 ex2_2(u64 a) {
    float lo, hi;
    asm("mov.b64 {%0, %1}, %2;" : "=f"(lo), "=f"(hi) : "l"(a));
    return pack2(ex2f(lo), ex2f(hi));
}
__device__ __forceinline__ u64 d2u(double d) { return __double_as_longlong(d); }

__global__ void sm_precompute(const float* __restrict__ x,
                              const float* __restrict__ y,
                              const float* __restrict__ lw,
                              const float* __restrict__ rm,
                              const float* __restrict__ lv)
{
    int idx = blockIdx.x * blockDim.x + threadIdx.x;
    if (idx >= NN + MM) return;
    bool isx = idx < NN;
    int row = isx ? idx : idx - NN;

    const float* t = (isx ? x : y) + row * 4;
    float td[4];
#pragma unroll
    for (int d = 0; d < 4; d++) td[d] = t[d];

#pragma unroll
    for (int q = 0; q < 4; q++) {
        float a = 0.0f;
        float c[4], s[4], vq[4];
#pragma unroll
        for (int d = 0; d < 4; d++) {
            vq[d] = expf(lv[q * 4 + d]);
            a = fmaf(vq[d], td[d] * td[d], a);
            float th = TWOPI * rm[q * 4 + d] * td[d];
            sincosf(th, &s[d], &c[d]);
        }
        float P[8];
        P[0] = c[0] * c[1]; P[1] = c[0] * s[1]; P[2] = s[0] * c[1]; P[3] = s[0] * s[1];
        P[4] = c[2] * c[3]; P[5] = c[2] * s[3]; P[6] = s[2] * c[3]; P[7] = s[2] * s[3];

        if (isx) {
            float* o = (float*)g_x + row * 80;
            float Aq = GCONST * a;
            o[2 * q] = Aq; o[2 * q + 1] = Aq;
            if (q == 0) {
#pragma unroll
                for (int d = 0; d < 4; d++) { o[8 + 2 * d] = td[d]; o[9 + 2 * d] = td[d]; }
            }
            float* b = o + 16 + 16 * q;
#pragma unroll
            for (int k = 0; k < 4; k++) { b[2 * k] = P[k];      b[2 * k + 1] = P[k]; }
#pragma unroll
            for (int k = 0; k < 4; k++) { b[8 + 2 * k] = P[4 + k]; b[9 + 2 * k] = P[4 + k]; }
        } else {
            float* o = (float*)g_y + (row >> 1) * 108;
            int sl = row & 1;
            o[2 * q + sl] = GCONST * a + lw[q] * LOG2E;
            float* b = o + 8 + 24 * q;
#pragma unroll
            for (int d = 0; d < 4; d++) b[2 * d + sl] = -2.0f * GCONST * vq[d] * td[d];
#pragma unroll
            for (int k = 0; k < 4; k++) b[8 + 2 * k + sl] = P[k];
#pragma unroll
            for (int k = 0; k < 4; k++) b[16 + 2 * k + sl] = P[4 + k];
        }
    }
}

// Block tile: 64 x-rows x 64 y-cols. 128 threads (8 ti x 16 tj),
// thread tile I=8 rows, C=2 pair-cols — SAME per-thread work as the
// 117us kernel, but 128-thread blocks raise the reg cap to ~168
// (65536/384), giving ptxas room to fully unroll q, hoist the
// q-invariant x loads, and statically pipeline without spilling.
// Static smem (34.3 KB < 48 KB) — no dynamic-smem attribute needed.
__global__ void __launch_bounds__(128, 3)
sm_main(float* __restrict__ out)
{
    __shared__ float sx[64 * 80];    // 20 KB
    __shared__ float sy[32 * 108];   // 13.5 KB

    const int n0 = blockIdx.y * 64;
    const int m0 = blockIdx.x * 64;

    {
        const float4* gx = g_x + n0 * 20;
        float4* s4 = (float4*)sx;
#pragma unroll 1
        for (int i = threadIdx.x; i < 1280; i += 128) s4[i] = gx[i];
        const float4* gy = g_y + (m0 / 2) * 27;
        float4* t4 = (float4*)sy;
#pragma unroll 1
        for (int i = threadIdx.x; i < 864; i += 128) t4[i] = gy[i];
    }
    __syncthreads();

    const int ti = threadIdx.x >> 4;   // 0..7 : rows ti + 8*i, i<8
    const int tj = threadIdx.x & 15;   // 0..15 : pair-cols tj + 16*c, c<2

    const float* xbase = sx + ti * 80;
    const float* yb0 = sy + tj * 108;
    const float* yb1 = sy + (tj + 16) * 108;

    u64 acc[8][2];
#pragma unroll
    for (int i = 0; i < 8; i++) { acc[i][0] = 0ull; acc[i][1] = 0ull; }

#pragma unroll
    for (int q = 0; q < 4; q++) {
        // --- load full y working set for this q (2 pair-records, 13 u64 each) ---
        u64 Bp[2], Wp[2][4], Ya[2][4], Yb[2][4];
#pragma unroll
        for (int c = 0; c < 2; c++) {
            const float* yr = (c == 0) ? yb0 : yb1;
            Bp[c] = *(const u64*)(yr + 2 * q);
            const float* yq = yr + 8 + 24 * q;
            double2 w0 = *(const double2*)(yq);
            double2 w1 = *(const double2*)(yq + 4);
            Wp[c][0] = d2u(w0.x); Wp[c][1] = d2u(w0.y);
            Wp[c][2] = d2u(w1.x); Wp[c][3] = d2u(w1.y);
            double2 a0 = *(const double2*)(yq + 8);
            double2 a1 = *(const double2*)(yq + 12);
            Ya[c][0] = d2u(a0.x); Ya[c][1] = d2u(a0.y);
            Ya[c][2] = d2u(a1.x); Ya[c][3] = d2u(a1.y);
            double2 b0 = *(const double2*)(yq + 16);
            double2 b1 = *(const double2*)(yq + 20);
            Yb[c][0] = d2u(b0.x); Yb[c][1] = d2u(b0.y);
            Yb[c][2] = d2u(b1.x); Yb[c][3] = d2u(b1.y);
        }

        // --- stream 8 x-rows against the registered y data ---
#pragma unroll
        for (int i = 0; i < 8; i++) {
            const float* xr = xbase + i * 640;        // (ti + 8*i) * 80
            u64 Ap = *(const u64*)(xr + 2 * q);
            double2 x0 = *(const double2*)(xr + 8);
            double2 x1 = *(const double2*)(xr + 12);
            u64 xp0 = d2u(x0.x), xp1 = d2u(x0.y), xp2 = d2u(x1.x), xp3 = d2u(x1.y);
            const float* xq = xr + 16 + 16 * q;
            double2 p0 = *(const double2*)(xq);
            double2 p1 = *(const double2*)(xq + 4);
            double2 r0 = *(const double2*)(xq + 8);
            double2 r1 = *(const double2*)(xq + 12);
            u64 Xa0 = d2u(p0.x), Xa1 = d2u(p0.y), Xa2 = d2u(p1.x), Xa3 = d2u(p1.y);
            u64 Xb0 = d2u(r0.x), Xb1 = d2u(r0.y), Xb2 = d2u(r1.x), Xb3 = d2u(r1.y);

#pragma unroll
            for (int c = 0; c < 2; c++) {
                u64 arg = add2(Ap, Bp[c]);
                arg = fma2(xp0, Wp[c][0], arg);
                arg = fma2(xp1, Wp[c][1], arg);
                arg = fma2(xp2, Wp[c][2], arg);
                arg = fma2(xp3, Wp[c][3], arg);
                u64 e = ex2_2(arg);
                u64 ta = mul2(Xa0, Ya[c][0]);
                ta = fma2(Xa1, Ya[c][1], ta);
                ta = fma2(Xa2, Ya[c][2], ta);
                ta = fma2(Xa3, Ya[c][3], ta);
                u64 tb = mul2(Xb0, Yb[c][0]);
                tb = fma2(Xb1, Yb[c][1], tb);
                tb = fma2(Xb2, Yb[c][2], tb);
                tb = fma2(Xb3, Yb[c][3], tb);
                acc[i][c] = fma2(e, mul2(ta, tb), acc[i][c]);
            }
        }
    }

#pragma unroll
    for (int i = 0; i < 8; i++) {
        float* row = out + (size_t)(n0 + ti + 8 * i) * MM + m0 + 2 * tj;
        *(u64*)(row)      = acc[i][0];
        *(u64*)(row + 32) = acc[i][1];
    }
}

extern "C" void kernel_launch(void* const* d_in, const int* in_sizes, int n_in,
                              void* d_out, int out_size)
{
    const float* x  = (const float*)d_in[0];
    const float* y  = (const float*)d_in[1];
    const float* lw = (const float*)d_in[2];
    const float* rm = (const float*)d_in[3];
    const float* lv = (const float*)d_in[4];
    float* out = (float*)d_out;

    sm_precompute<<<(NN + MM + 255) / 256, 256>>>(x, y, lw, rm, lv);

    dim3 grid(MM / 64, NN / 64);
    sm_main<<<grid, 128>>>(out);
}